// round 15
// baseline (speedup 1.0000x reference)
#include <cuda_runtime.h>
#include <cuda_bf16.h>
#include <cstdint>

#define DINLINE __device__ __forceinline__

// ---------------- problem sizes ----------------
#define B_  64
#define TN_ 131072
#define TE_ 262144
#define TT_ (TN_ + TE_)
#define QD_ 768
#define PD_ 512
#define KD_ 512

// ---------------- device scratch ----------------
__device__ float g_qn[B_ * PD_];
__device__ float g_qe[B_ * PD_];
__device__ __nv_bfloat16 g_wtn[PD_ * KD_];   // W_n transposed [P][K], bf16
__device__ __nv_bfloat16 g_wte[PD_ * KD_];
__device__ float g_part[4 * TT_];            // per-N-slice partial sums (no init needed)
__device__ float g_sum[128];                 // per-graph exp sums
__device__ int   g_ctr;                      // k_soft spin-barrier counter
__device__ int   g_qctr;                     // qproj completion counter
__device__ int   g_qflag;                    // qproj done flag

// ---------------- helpers ----------------
DINLINE void cp16(uint32_t s, const void* g) {
    asm volatile("cp.async.cg.shared.global [%0], [%1], 16;"
                 :: "r"(s), "l"(g) : "memory");
}
DINLINE void cp_commit() { asm volatile("cp.async.commit_group;" ::: "memory"); }
template<int N> DINLINE void cp_wait() {
    asm volatile("cp.async.wait_group %0;" :: "n"(N) : "memory");
}

DINLINE uint32_t smem_u32(const void* p) {
    uint32_t a;
    asm("{ .reg .u64 t; cvta.to.shared.u64 t, %1; cvt.u32.u64 %0, t; }"
        : "=r"(a) : "l"(p));
    return a;
}

DINLINE float tanh_fast(float x) {
    float y;
    asm("tanh.approx.f32 %0, %1;" : "=f"(y) : "f"(x));
    return y;
}

DINLINE void mma_bf16(float* c, const uint32_t* a, const uint32_t* b) {
    asm volatile(
        "mma.sync.aligned.m16n8k16.row.col.f32.bf16.bf16.f32 "
        "{%0,%1,%2,%3}, {%4,%5,%6,%7}, {%8,%9}, {%0,%1,%2,%3};"
        : "+f"(c[0]), "+f"(c[1]), "+f"(c[2]), "+f"(c[3])
        : "r"(a[0]), "r"(a[1]), "r"(a[2]), "r"(a[3]),
          "r"(b[0]), "r"(b[1]));
}

DINLINE void ldm_x4(uint32_t& r0, uint32_t& r1, uint32_t& r2, uint32_t& r3,
                    uint32_t addr) {
    asm volatile("ldmatrix.sync.aligned.m8n8.x4.shared.b16 {%0,%1,%2,%3}, [%4];"
                 : "=r"(r0), "=r"(r1), "=r"(r2), "=r"(r3) : "r"(addr));
}

DINLINE uint32_t pack_bf16x2(float lo, float hi) {
    __nv_bfloat162 v = __float22bfloat162_rn(make_float2(lo, hi));
    return *reinterpret_cast<uint32_t*>(&v);
}

// ---------------- main fused GEMM ----------------
#define ROWB   80u
#define ATILE  20480u
#define BTILE  10240u
#define BOFF   40960u
#define SM_OFF 71680u
#define SMEM_BYTES (71680 + 1024)
#define NYN 512              // node tiles in y

__global__ void __launch_bounds__(256, 1) k_main(
    const float* __restrict__ An, const float* __restrict__ Ae,
    const int* __restrict__ gidN, const int* __restrict__ gidE,
    const __nv_bfloat16* __restrict__ WtN, const __nv_bfloat16* __restrict__ WtE,
    const float* __restrict__ qN, const float* __restrict__ qE,
    const float* __restrict__ wvN, const float* __restrict__ wvE,
    float* __restrict__ part)
{
    extern __shared__ char smem[];
    float* s_sm = reinterpret_cast<float*>(smem + SM_OFF);

    const bool isNode = blockIdx.y < NYN;
    const int  ty     = isNode ? blockIdx.y : blockIdx.y - NYN;
    const float* __restrict__ A    = isNode ? An   : Ae;
    const int*   __restrict__ gid  = isNode ? gidN : gidE;
    const __nv_bfloat16* __restrict__ Wt = isNode ? WtN : WtE;
    const float* __restrict__ qeff = isNode ? qN   : qE;
    const float* __restrict__ wv   = isNode ? wvN  : wvE;
    const int    sOff = isNode ? 0 : TN_;

    const int tid  = threadIdx.x;
    const int lane = tid & 31;
    const int warp = tid >> 5;
    const int wm   = warp & 3;   // M block of 64
    const int wn   = warp >> 2;  // N block of 64

    const int mBase = ty * 256;
    const int nBase = blockIdx.x * 128;

    const uint32_t sb = smem_u32(smem);

    s_sm[tid] = 0.f;

    // ---- A loader: 256 rows x 32 f32 per chunk; thread: 8 float4
    const int aRow = tid >> 3;
    const int aQ   = tid & 7;
    const float* Abase = A + (size_t)(mBase + aRow) * KD_ + aQ * 4;

    float4 ra[8];
    auto ldA = [&](int kc) {
        const float* p = Abase + kc * 32;
#pragma unroll
        for (int i = 0; i < 8; ++i)
            ra[i] = *reinterpret_cast<const float4*>(p + (size_t)i * 32 * KD_);
    };
    auto stsA = [&](int buf) {
        const uint32_t base = sb + buf * ATILE + aRow * ROWB + aQ * 8;
#pragma unroll
        for (int i = 0; i < 8; ++i) {
            uint32_t lo = pack_bf16x2(ra[i].x, ra[i].y);
            uint32_t hi = pack_bf16x2(ra[i].z, ra[i].w);
            asm volatile("st.shared.v2.b32 [%0], {%1,%2};"
                         :: "r"(base + i * 32 * ROWB), "r"(lo), "r"(hi) : "memory");
        }
    };
    const int bIdx0 = tid * 2;
    auto cpB = [&](int slot, int kc) {
#pragma unroll
        for (int j = 0; j < 2; ++j) {
            int idx = bIdx0 + j;
            int n = idx >> 2, g = idx & 3;
            cp16(sb + BOFF + slot * BTILE + n * ROWB + g * 16,
                 Wt + (size_t)(nBase + n) * KD_ + kc * 32 + g * 8);
        }
        cp_commit();
    };

    float c[4][8][4];
#pragma unroll
    for (int mt = 0; mt < 4; ++mt)
#pragma unroll
        for (int nt = 0; nt < 8; ++nt)
#pragma unroll
            for (int i = 0; i < 4; ++i) c[mt][nt][i] = 0.f;

    // ---- ldmatrix per-lane offsets ----
    const int j = lane >> 3;
    const uint32_t aLane = (uint32_t)(wm * 64 + ((j & 1) << 3) + (lane & 7)) * ROWB
                         + (uint32_t)(j >> 1) * 16u;
    const uint32_t bLane = (uint32_t)(wn * 64 + ((j >> 1) << 3) + (lane & 7)) * ROWB
                         + (uint32_t)(j & 1) * 16u;

    uint32_t aF0[4][4], aF1[4][4];

    auto ldA_frags = [&](uint32_t aT2, uint32_t ko, uint32_t (&a)[4][4]) {
#pragma unroll
        for (int mt = 0; mt < 4; ++mt)
            ldm_x4(a[mt][0], a[mt][1], a[mt][2], a[mt][3],
                   aT2 + mt * 16 * ROWB + ko);
    };

    auto phase = [&](const uint32_t (&aIn)[4][4], uint32_t (&aOut)[4][4],
                     uint32_t bT2, uint32_t ko,
                     uint32_t aT2n, uint32_t kon, bool preloadA) {
        uint32_t b[2][2][2];
        ldm_x4(b[0][0][0], b[0][0][1], b[0][1][0], b[0][1][1], bT2 + ko);
#pragma unroll
        for (int p = 0; p < 4; ++p) {
            const int cb = p & 1, nb = cb ^ 1;
            if (p < 3) {
                ldm_x4(b[nb][0][0], b[nb][0][1], b[nb][1][0], b[nb][1][1],
                       bT2 + (uint32_t)(p + 1) * 16 * ROWB + ko);
            } else if (preloadA) {
                ldA_frags(aT2n, kon, aOut);
            }
#pragma unroll
            for (int mt = 0; mt < 4; ++mt) {
                mma_bf16(c[mt][2 * p],     aIn[mt], b[cb][0]);
                mma_bf16(c[mt][2 * p + 1], aIn[mt], b[cb][1]);
            }
        }
    };

    // ---- preamble ----
    ldA(0);
    cpB(0, 0);
    cpB(1, 1);
    stsA(0);
    ldA(1);
    cp_wait<1>();
    __syncthreads();
    ldA_frags(sb + aLane, 0, aF0);

#pragma unroll 1
    for (int kc = 0; kc < 16; ++kc) {
        const int abuf = kc & 1;
        if (kc + 2 < 16) cpB((kc + 2) % 3, kc + 2);

        const uint32_t aT2 = sb + abuf * ATILE + aLane;
        const uint32_t bT2 = sb + BOFF + (kc % 3) * BTILE + bLane;

        phase(aF0, aF1, bT2, 0, aT2, 32, true);
        if (kc + 1 < 16) stsA(abuf ^ 1);
        if (kc + 2 < 16) ldA(kc + 2);
        phase(aF1, aF0, bT2, 32, 0, 0, false);

        if (kc + 2 < 16) cp_wait<1>(); else cp_wait<0>();
        __syncthreads();
        if (kc + 1 < 16)
            ldA_frags(sb + (abuf ^ 1) * ATILE + aLane, 0, aF0);
    }

    // ---- wait for concurrent k_qproj (qeff producer) before epilogue ----
    if (tid == 0) {
        volatile int* f = &g_qflag;
        while (*f == 0) { }
    }
    __syncthreads();
    __threadfence();

    // ---- epilogue: partial s[m] for this N-slice; no global atomics ----
    const int n0 = wn * 64 + 2 * (lane & 3);
#pragma unroll
    for (int mt = 0; mt < 4; ++mt) {
#pragma unroll
        for (int h = 0; h < 2; ++h) {
            const int row = wm * 64 + mt * 16 + (lane >> 2) + h * 8;
            const int g = __ldg(gid + mBase + row);
            const float* qrow = qeff + (size_t)g * PD_ + nBase;
            float s = 0.f;
#pragma unroll
            for (int nt = 0; nt < 8; ++nt) {
                const int nn = n0 + nt * 8;
                float2 q2 = *reinterpret_cast<const float2*>(qrow + nn);
                float2 w2 = *reinterpret_cast<const float2*>(wv + nBase + nn);
                float x0 = tanh_fast(c[mt][nt][h * 2 + 0] + q2.x);
                float x1 = tanh_fast(c[mt][nt][h * 2 + 1] + q2.y);
                s = fmaf(x0, w2.x, s);
                s = fmaf(x1, w2.y, s);
            }
            s += __shfl_xor_sync(0xffffffffu, s, 1);
            s += __shfl_xor_sync(0xffffffffu, s, 2);
            if ((lane & 3) == 0) atomicAdd(&s_sm[row], s);
        }
    }
    __syncthreads();
    part[(size_t)blockIdx.x * TT_ + sOff + mBase + tid] = s_sm[tid];
}

// ---------------- prep: transposes + scratch zeroing, one launch ----------------
__global__ void __launch_bounds__(256) k_prep(
    const float* __restrict__ Wn, const float* __restrict__ We,
    __nv_bfloat16* __restrict__ WtN, __nv_bfloat16* __restrict__ WtE,
    float* __restrict__ qn, float* __restrict__ qe,
    float* __restrict__ gsum, int* __restrict__ ctr,
    int* __restrict__ qctr, int* __restrict__ qflag) {
    const int blk = blockIdx.x;
    const int t = threadIdx.x;
    if (blk == 544) {
        if (t < 128) gsum[t] = 0.f;
        if (t == 128) *ctr = 0;
        if (t == 129) *qctr = 0;
        if (t == 130) *qflag = 0;
        return;
    }
    if (blk >= 512) {
        const int zi = blk - 512;
        float* dst = (zi < 16) ? (qn + zi * 2048) : (qe + (zi - 16) * 2048);
#pragma unroll
        for (int k = 0; k < 8; ++k) dst[k * 256 + t] = 0.f;
        return;
    }
    const bool isE = blk >= 256;
    const int b2 = blk & 255;
    const float* W = isE ? We : Wn;
    __nv_bfloat16* Wt = isE ? WtE : WtN;
    __shared__ float tile[32][33];
    const int tx = t & 31, ty2 = t >> 5;
    int x = (b2 & 15) * 32 + tx;
    int y = (b2 >> 4) * 32 + ty2;
#pragma unroll
    for (int j = 0; j < 32; j += 8)
        tile[ty2 + j][tx] = W[(y + j) * 512 + x];
    __syncthreads();
    int xo = (b2 >> 4) * 32 + tx;
    int yo = (b2 & 15) * 32 + ty2;
#pragma unroll
    for (int j = 0; j < 32; j += 8)
        Wt[(yo + j) * 512 + xo] = __float2bfloat16(tile[tx][ty2 + j]);
}

// split-k qproj, grid (B_, 16, 2) = 2048 blocks; sets g_qflag when ALL done.
__global__ void __launch_bounds__(256) k_qproj(
    const float* __restrict__ q,
    const float* __restrict__ WqN, const float* __restrict__ bqN, const float* __restrict__ bhN,
    const float* __restrict__ WqE, const float* __restrict__ bqE, const float* __restrict__ bhE,
    float* __restrict__ outN, float* __restrict__ outE,
    int* __restrict__ qctr, int* __restrict__ qflag) {
    const float* Wq = blockIdx.z ? WqE : WqN;
    const float* bq = blockIdx.z ? bqE : bqN;
    const float* bh = blockIdx.z ? bhE : bhN;
    float* out = blockIdx.z ? outE : outN;
    __shared__ float qs[48];
    const int b = blockIdx.x, ks = blockIdx.y;
    const int k0 = ks * 48;
    const int t = threadIdx.x;
    if (t < 48) qs[t] = q[b * QD_ + k0 + t];
    __syncthreads();
    const int p0 = t, p1 = t + 256;
    float a0 = 0.f, a1 = 0.f;
#pragma unroll 4
    for (int k = 0; k < 48; ++k) {
        const float* wrow = Wq + (size_t)(k0 + k) * 512;
        a0 = fmaf(qs[k], __ldg(wrow + p0), a0);
        a1 = fmaf(qs[k], __ldg(wrow + p1), a1);
    }
    if (ks == 0) {
        a0 += __ldg(bq + p0) + __ldg(bh + p0);
        a1 += __ldg(bq + p1) + __ldg(bh + p1);
    }
    atomicAdd(out + b * 512 + p0, a0);
    atomicAdd(out + b * 512 + p1, a1);

    // completion protocol: last of 2048 blocks raises the flag
    __syncthreads();
    __threadfence();
    if (t == 0) {
        int old = atomicAdd(qctr, 1);
        if (old == 2 * B_ * 16 - 1) {
            __threadfence();
            *qflag = 1;
        }
    }
}

// ---------------- fused softmax (no max-shift; |s| <= ~9 so exp is fp32-safe) ----
// grid 768 (chunk 512); all co-resident (6 blocks/SM needed <= 8 cap).
__global__ void __launch_bounds__(256) k_soft(
    const float* __restrict__ part,
    const int* __restrict__ gidN, const int* __restrict__ gidE,
    float* __restrict__ gsum, int* __restrict__ ctr,
    float* __restrict__ out) {
    __shared__ float ssum[128];
    const int t = threadIdx.x;
    if (t < 128) ssum[t] = 0.f;
    __syncthreads();
    const int base = blockIdx.x * 512;
    const bool isNode = base < TN_;          // 512 divides TN_: no straddle
    const int* gid = isNode ? gidN : gidE;
    const int lofs = isNode ? 0 : TN_;
    const int goff = isNode ? 0 : 64;

    float ev[2];
    int   gv[2];
#pragma unroll
    for (int jj = 0; jj < 2; ++jj) {
        const int i = base + jj * 256 + t;
        float v = __ldg(part + i)
                + __ldg(part + TT_ + i)
                + __ldg(part + 2 * TT_ + i)
                + __ldg(part + 3 * TT_ + i);
        float e = __expf(v);
        ev[jj] = e;
        const int g = __ldg(gid + i - lofs);
        gv[jj] = goff + g;
        const int g0 = __shfl_sync(0xffffffffu, g, 0);
        if (__all_sync(0xffffffffu, g == g0)) {
            float r = e;
            r += __shfl_xor_sync(0xffffffffu, r, 16);
            r += __shfl_xor_sync(0xffffffffu, r, 8);
            r += __shfl_xor_sync(0xffffffffu, r, 4);
            r += __shfl_xor_sync(0xffffffffu, r, 2);
            r += __shfl_xor_sync(0xffffffffu, r, 1);
            if ((t & 31) == 0) atomicAdd(&ssum[goff + g0], r);
        } else {
            atomicAdd(&ssum[goff + g], e);
        }
    }
    __syncthreads();
    if (t < 128 && ssum[t] != 0.f) atomicAdd(&gsum[t], ssum[t]);

    // ---- device-wide barrier ----
    __threadfence();
    __syncthreads();
    if (t == 0) {
        atomicAdd(ctr, 1);
        volatile int* vc = ctr;
        while (*vc < (int)gridDim.x) { }
    }
    __syncthreads();
    __threadfence();

    // ---- normalize from registers ----
#pragma unroll
    for (int jj = 0; jj < 2; ++jj) {
        const int i = base + jj * 256 + t;
        float z = __ldcg(gsum + gv[jj]);
        out[i] = __fdividef(ev[jj], z);
    }
}

// ---------------- launch ----------------
extern "C" void kernel_launch(void* const* d_in, const int* in_sizes, int n_in,
                              void* d_out, int out_size) {
    const float* question = (const float*)d_in[0];
    const float* nodes    = (const float*)d_in[1];
    const float* edges    = (const float*)d_in[2];
    const float* W_nq     = (const float*)d_in[3];
    const float* b_nq     = (const float*)d_in[4];
    const float* W_n      = (const float*)d_in[5];
    const float* b_n      = (const float*)d_in[6];
    const float* w_nv     = (const float*)d_in[7];
    // d_in[8] = b_nv — softmax shift-invariant, unused
    const float* W_eq     = (const float*)d_in[9];
    const float* b_eq     = (const float*)d_in[10];
    const float* W_e      = (const float*)d_in[11];
    const float* b_e      = (const float*)d_in[12];
    const float* w_ev     = (const float*)d_in[13];
    // d_in[14] = b_ev — unused
    const int* node_gid   = (const int*)d_in[15];
    const int* edge_gid   = (const int*)d_in[16];
    float* out = (float*)d_out;

    float *qn, *qe, *part, *gsum;
    int *ctr, *qctr, *qflag;
    __nv_bfloat16 *wtn, *wte;
    cudaGetSymbolAddress((void**)&qn,    g_qn);
    cudaGetSymbolAddress((void**)&qe,    g_qe);
    cudaGetSymbolAddress((void**)&wtn,   g_wtn);
    cudaGetSymbolAddress((void**)&wte,   g_wte);
    cudaGetSymbolAddress((void**)&part,  g_part);
    cudaGetSymbolAddress((void**)&gsum,  g_sum);
    cudaGetSymbolAddress((void**)&ctr,   g_ctr);
    cudaGetSymbolAddress((void**)&qctr,  g_qctr);
    cudaGetSymbolAddress((void**)&qflag, g_qflag);

    cudaFuncSetAttribute(k_main, cudaFuncAttributeMaxDynamicSharedMemorySize, SMEM_BYTES);

    // fresh fork/join handles each call (no static caching; host-side only)
    cudaStream_t s2;
    cudaEvent_t evA, evB;
    cudaStreamCreateWithFlags(&s2, cudaStreamNonBlocking);
    cudaEventCreateWithFlags(&evA, cudaEventDisableTiming);
    cudaEventCreateWithFlags(&evB, cudaEventDisableTiming);

    // main stream: prep (transposes, zeroing)
    k_prep<<<545, 256>>>(W_n, W_e, wtn, wte, qn, qe, gsum, ctr, qctr, qflag);

    // fork: qproj runs concurrently with k_main; k_main's epilogue spin-waits
    // on g_qflag, so the data dependency is enforced on-device.
    cudaEventRecord(evA, 0);
    cudaStreamWaitEvent(s2, evA, 0);
    k_qproj<<<dim3(B_, 16, 2), 256, 0, s2>>>(question,
                                             W_nq, b_nq, b_n,
                                             W_eq, b_eq, b_e, qn, qe,
                                             qctr, qflag);
    cudaEventRecord(evB, s2);

    k_main<<<dim3(4, NYN + TE_ / 256), 256, SMEM_BYTES>>>(
        nodes, edges, node_gid, edge_gid, wtn, wte, qn, qe, w_nv, w_ev, part);

    // join before the softmax consumes qproj-dependent results
    cudaStreamWaitEvent(0, evB, 0);
    k_soft<<<TT_ / 512, 256>>>(part, node_gid, edge_gid, gsum, ctr, out);
}

// round 16
// speedup vs baseline: 1.0634x; 1.0634x over previous
#include <cuda_runtime.h>
#include <cuda_bf16.h>
#include <cstdint>

#define DINLINE __device__ __forceinline__

// ---------------- problem sizes ----------------
#define B_  64
#define TN_ 131072
#define TE_ 262144
#define TT_ (TN_ + TE_)
#define QD_ 768
#define PD_ 512
#define KD_ 512
#define NTILES 1536

// ---------------- device scratch ----------------
__device__ float g_qn[B_ * PD_];
__device__ float g_qe[B_ * PD_];
__device__ __nv_bfloat16 g_wtn[PD_ * KD_];   // W_n transposed [P][K], bf16
__device__ __nv_bfloat16 g_wte[PD_ * KD_];
__device__ float g_part[4 * TT_];            // per-N-slice partial sums (no init needed)
__device__ float g_e[TT_];                   // exp(score) (no init needed)
__device__ float g_sum[128];                 // per-graph exp sums
__device__ int   g_tctr[NTILES];             // per-tile completion counters

// ---------------- helpers ----------------
DINLINE void cp16(uint32_t s, const void* g) {
    asm volatile("cp.async.cg.shared.global [%0], [%1], 16;"
                 :: "r"(s), "l"(g) : "memory");
}
DINLINE void cp_commit() { asm volatile("cp.async.commit_group;" ::: "memory"); }
template<int N> DINLINE void cp_wait() {
    asm volatile("cp.async.wait_group %0;" :: "n"(N) : "memory");
}

DINLINE uint32_t smem_u32(const void* p) {
    uint32_t a;
    asm("{ .reg .u64 t; cvta.to.shared.u64 t, %1; cvt.u32.u64 %0, t; }"
        : "=r"(a) : "l"(p));
    return a;
}

DINLINE float tanh_fast(float x) {
    float y;
    asm("tanh.approx.f32 %0, %1;" : "=f"(y) : "f"(x));
    return y;
}

DINLINE void mma_bf16(float* c, const uint32_t* a, const uint32_t* b) {
    asm volatile(
        "mma.sync.aligned.m16n8k16.row.col.f32.bf16.bf16.f32 "
        "{%0,%1,%2,%3}, {%4,%5,%6,%7}, {%8,%9}, {%0,%1,%2,%3};"
        : "+f"(c[0]), "+f"(c[1]), "+f"(c[2]), "+f"(c[3])
        : "r"(a[0]), "r"(a[1]), "r"(a[2]), "r"(a[3]),
          "r"(b[0]), "r"(b[1]));
}

DINLINE void ldm_x4(uint32_t& r0, uint32_t& r1, uint32_t& r2, uint32_t& r3,
                    uint32_t addr) {
    asm volatile("ldmatrix.sync.aligned.m8n8.x4.shared.b16 {%0,%1,%2,%3}, [%4];"
                 : "=r"(r0), "=r"(r1), "=r"(r2), "=r"(r3) : "r"(addr));
}

DINLINE uint32_t pack_bf16x2(float lo, float hi) {
    __nv_bfloat162 v = __float22bfloat162_rn(make_float2(lo, hi));
    return *reinterpret_cast<uint32_t*>(&v);
}

// ---------------- main fused GEMM ----------------
// CTA: 256 threads (8 warps, 4 wm x 2 wn, warp tile 64x64).
// Tile: M=256, N=128 (blockIdx.x in 0..3), K=512 in 16 chunks of 32.
// blockIdx.y in [0,1536): y<512 -> nodes; else edges.
#define ROWB   80u
#define ATILE  20480u
#define BTILE  10240u
#define BOFF   40960u
#define SM_OFF 71680u
#define SMEM_BYTES (71680 + 1024)
#define NYN 512              // node tiles in y

__global__ void __launch_bounds__(256, 1) k_main(
    const float* __restrict__ An, const float* __restrict__ Ae,
    const int* __restrict__ gidN, const int* __restrict__ gidE,
    const __nv_bfloat16* __restrict__ WtN, const __nv_bfloat16* __restrict__ WtE,
    const float* __restrict__ qN, const float* __restrict__ qE,
    const float* __restrict__ wvN, const float* __restrict__ wvE,
    float* __restrict__ part, float* __restrict__ ebuf,
    float* __restrict__ gsum, int* __restrict__ tctr)
{
    extern __shared__ char smem[];
    float* s_sm = reinterpret_cast<float*>(smem + SM_OFF);

    const bool isNode = blockIdx.y < NYN;
    const int  ty     = isNode ? blockIdx.y : blockIdx.y - NYN;
    const float* __restrict__ A    = isNode ? An   : Ae;
    const int*   __restrict__ gid  = isNode ? gidN : gidE;
    const __nv_bfloat16* __restrict__ Wt = isNode ? WtN : WtE;
    const float* __restrict__ qeff = isNode ? qN   : qE;
    const float* __restrict__ wv   = isNode ? wvN  : wvE;
    const int    sOff = isNode ? 0 : TN_;
    const int    goff = isNode ? 0 : 64;

    const int tid  = threadIdx.x;
    const int lane = tid & 31;
    const int warp = tid >> 5;
    const int wm   = warp & 3;   // M block of 64
    const int wn   = warp >> 2;  // N block of 64

    const int mBase = ty * 256;
    const int nBase = blockIdx.x * 128;

    const uint32_t sb = smem_u32(smem);

    s_sm[tid] = 0.f;

    // ---- A loader: 256 rows x 32 f32 per chunk; thread: 8 float4
    const int aRow = tid >> 3;
    const int aQ   = tid & 7;
    const float* Abase = A + (size_t)(mBase + aRow) * KD_ + aQ * 4;

    float4 ra[8];
    auto ldA = [&](int kc) {
        const float* p = Abase + kc * 32;
#pragma unroll
        for (int i = 0; i < 8; ++i)
            ra[i] = *reinterpret_cast<const float4*>(p + (size_t)i * 32 * KD_);
    };
    auto stsA = [&](int buf) {
        const uint32_t base = sb + buf * ATILE + aRow * ROWB + aQ * 8;
#pragma unroll
        for (int i = 0; i < 8; ++i) {
            uint32_t lo = pack_bf16x2(ra[i].x, ra[i].y);
            uint32_t hi = pack_bf16x2(ra[i].z, ra[i].w);
            asm volatile("st.shared.v2.b32 [%0], {%1,%2};"
                         :: "r"(base + i * 32 * ROWB), "r"(lo), "r"(hi) : "memory");
        }
    };
    const int bIdx0 = tid * 2;
    auto cpB = [&](int slot, int kc) {
#pragma unroll
        for (int j = 0; j < 2; ++j) {
            int idx = bIdx0 + j;
            int n = idx >> 2, g = idx & 3;
            cp16(sb + BOFF + slot * BTILE + n * ROWB + g * 16,
                 Wt + (size_t)(nBase + n) * KD_ + kc * 32 + g * 8);
        }
        cp_commit();
    };

    float c[4][8][4];
#pragma unroll
    for (int mt = 0; mt < 4; ++mt)
#pragma unroll
        for (int nt = 0; nt < 8; ++nt)
#pragma unroll
            for (int i = 0; i < 4; ++i) c[mt][nt][i] = 0.f;

    // ---- ldmatrix per-lane offsets ----
    const int j = lane >> 3;
    const uint32_t aLane = (uint32_t)(wm * 64 + ((j & 1) << 3) + (lane & 7)) * ROWB
                         + (uint32_t)(j >> 1) * 16u;
    const uint32_t bLane = (uint32_t)(wn * 64 + ((j >> 1) << 3) + (lane & 7)) * ROWB
                         + (uint32_t)(j & 1) * 16u;

    uint32_t aF0[4][4], aF1[4][4];

    auto ldA_frags = [&](uint32_t aT2, uint32_t ko, uint32_t (&a)[4][4]) {
#pragma unroll
        for (int mt = 0; mt < 4; ++mt)
            ldm_x4(a[mt][0], a[mt][1], a[mt][2], a[mt][3],
                   aT2 + mt * 16 * ROWB + ko);
    };

    auto phase = [&](const uint32_t (&aIn)[4][4], uint32_t (&aOut)[4][4],
                     uint32_t bT2, uint32_t ko,
                     uint32_t aT2n, uint32_t kon, bool preloadA) {
        uint32_t b[2][2][2];
        ldm_x4(b[0][0][0], b[0][0][1], b[0][1][0], b[0][1][1], bT2 + ko);
#pragma unroll
        for (int p = 0; p < 4; ++p) {
            const int cb = p & 1, nb = cb ^ 1;
            if (p < 3) {
                ldm_x4(b[nb][0][0], b[nb][0][1], b[nb][1][0], b[nb][1][1],
                       bT2 + (uint32_t)(p + 1) * 16 * ROWB + ko);
            } else if (preloadA) {
                ldA_frags(aT2n, kon, aOut);
            }
#pragma unroll
            for (int mt = 0; mt < 4; ++mt) {
                mma_bf16(c[mt][2 * p],     aIn[mt], b[cb][0]);
                mma_bf16(c[mt][2 * p + 1], aIn[mt], b[cb][1]);
            }
        }
    };

    // ---- preamble ----
    ldA(0);
    cpB(0, 0);
    cpB(1, 1);
    stsA(0);
    ldA(1);
    cp_wait<1>();
    __syncthreads();
    ldA_frags(sb + aLane, 0, aF0);

#pragma unroll 1
    for (int kc = 0; kc < 16; ++kc) {
        const int abuf = kc & 1;
        if (kc + 2 < 16) cpB((kc + 2) % 3, kc + 2);

        const uint32_t aT2 = sb + abuf * ATILE + aLane;
        const uint32_t bT2 = sb + BOFF + (kc % 3) * BTILE + bLane;

        phase(aF0, aF1, bT2, 0, aT2, 32, true);
        if (kc + 1 < 16) stsA(abuf ^ 1);
        if (kc + 2 < 16) ldA(kc + 2);
        phase(aF1, aF0, bT2, 32, 0, 0, false);

        if (kc + 2 < 16) cp_wait<1>(); else cp_wait<0>();
        __syncthreads();
        if (kc + 1 < 16)
            ldA_frags(sb + (abuf ^ 1) * ATILE + aLane, 0, aF0);
    }

    // ---- epilogue: partial s[m] for this N-slice ----
    const int n0 = wn * 64 + 2 * (lane & 3);
#pragma unroll
    for (int mt = 0; mt < 4; ++mt) {
#pragma unroll
        for (int h = 0; h < 2; ++h) {
            const int row = wm * 64 + mt * 16 + (lane >> 2) + h * 8;
            const int g = __ldg(gid + mBase + row);
            const float* qrow = qeff + (size_t)g * PD_ + nBase;
            float s = 0.f;
#pragma unroll
            for (int nt = 0; nt < 8; ++nt) {
                const int nn = n0 + nt * 8;
                float2 q2 = *reinterpret_cast<const float2*>(qrow + nn);
                float2 w2 = *reinterpret_cast<const float2*>(wv + nBase + nn);
                float x0 = tanh_fast(c[mt][nt][h * 2 + 0] + q2.x);
                float x1 = tanh_fast(c[mt][nt][h * 2 + 1] + q2.y);
                s = fmaf(x0, w2.x, s);
                s = fmaf(x1, w2.y, s);
            }
            s += __shfl_xor_sync(0xffffffffu, s, 1);
            s += __shfl_xor_sync(0xffffffffu, s, 2);
            if ((lane & 3) == 0) atomicAdd(&s_sm[row], s);
        }
    }
    __syncthreads();
    const int gi = sOff + mBase + tid;             // global score index
    part[(size_t)blockIdx.x * TT_ + gi] = s_sm[tid];

    // ---- tile-completion protocol: last of the 4 N-slice blocks combines ----
    __threadfence();
    __syncthreads();
    __shared__ int isLast;
    if (tid == 0)
        isLast = (atomicAdd(&tctr[blockIdx.y], 1) == 3);
    __syncthreads();
    if (!isLast) return;

    // combine 4 slices (own is still in s_sm), exp, per-graph sum
    float v = s_sm[tid];
    const int bx = blockIdx.x;
#pragma unroll
    for (int x = 0; x < 4; ++x)
        if (x != bx) v += __ldcg(part + (size_t)x * TT_ + gi);
    float e = __expf(v);
    ebuf[gi] = e;

    const int g = __ldg(gid + mBase + tid);
    const int g0 = __shfl_sync(0xffffffffu, g, 0);
    if (__all_sync(0xffffffffu, g == g0)) {
        float r = e;
        r += __shfl_xor_sync(0xffffffffu, r, 16);
        r += __shfl_xor_sync(0xffffffffu, r, 8);
        r += __shfl_xor_sync(0xffffffffu, r, 4);
        r += __shfl_xor_sync(0xffffffffu, r, 2);
        r += __shfl_xor_sync(0xffffffffu, r, 1);
        if (lane == 0) atomicAdd(&gsum[goff + g0], r);
    } else {
        atomicAdd(&gsum[goff + g], e);
    }
}

// ---------------- prep: transposes + scratch zeroing, one launch ----------------
// grid 551 x 256:
//   blk 0..255:   transpose W_n; blk 256..511: transpose W_e
//   blk 512..543: zero qn/qe; blk 544: zero gsum; blk 545..550: zero tctr
__global__ void __launch_bounds__(256) k_prep(
    const float* __restrict__ Wn, const float* __restrict__ We,
    __nv_bfloat16* __restrict__ WtN, __nv_bfloat16* __restrict__ WtE,
    float* __restrict__ qn, float* __restrict__ qe,
    float* __restrict__ gsum, int* __restrict__ tctr) {
    const int blk = blockIdx.x;
    const int t = threadIdx.x;
    if (blk >= 545) {
        tctr[(blk - 545) * 256 + t] = 0;
        return;
    }
    if (blk == 544) {
        if (t < 128) gsum[t] = 0.f;
        return;
    }
    if (blk >= 512) {
        const int zi = blk - 512;
        float* dst = (zi < 16) ? (qn + zi * 2048) : (qe + (zi - 16) * 2048);
#pragma unroll
        for (int k = 0; k < 8; ++k) dst[k * 256 + t] = 0.f;
        return;
    }
    const bool isE = blk >= 256;
    const int b2 = blk & 255;
    const float* W = isE ? We : Wn;
    __nv_bfloat16* Wt = isE ? WtE : WtN;
    __shared__ float tile[32][33];
    const int tx = t & 31, ty2 = t >> 5;
    int x = (b2 & 15) * 32 + tx;
    int y = (b2 >> 4) * 32 + ty2;
#pragma unroll
    for (int j = 0; j < 32; j += 8)
        tile[ty2 + j][tx] = W[(y + j) * 512 + x];
    __syncthreads();
    int xo = (b2 >> 4) * 32 + tx;
    int yo = (b2 & 15) * 32 + ty2;
#pragma unroll
    for (int j = 0; j < 32; j += 8)
        Wt[(yo + j) * 512 + xo] = __float2bfloat16(tile[tx][ty2 + j]);
}

// split-k qproj, grid (B_, 16, 2): k-slice 48; z selects node/edge weights.
__global__ void __launch_bounds__(256) k_qproj(
    const float* __restrict__ q,
    const float* __restrict__ WqN, const float* __restrict__ bqN, const float* __restrict__ bhN,
    const float* __restrict__ WqE, const float* __restrict__ bqE, const float* __restrict__ bhE,
    float* __restrict__ outN, float* __restrict__ outE) {
    const float* Wq = blockIdx.z ? WqE : WqN;
    const float* bq = blockIdx.z ? bqE : bqN;
    const float* bh = blockIdx.z ? bhE : bhN;
    float* out = blockIdx.z ? outE : outN;
    __shared__ float qs[48];
    const int b = blockIdx.x, ks = blockIdx.y;
    const int k0 = ks * 48;
    const int t = threadIdx.x;
    if (t < 48) qs[t] = q[b * QD_ + k0 + t];
    __syncthreads();
    const int p0 = t, p1 = t + 256;
    float a0 = 0.f, a1 = 0.f;
#pragma unroll 4
    for (int k = 0; k < 48; ++k) {
        const float* wrow = Wq + (size_t)(k0 + k) * 512;
        a0 = fmaf(qs[k], __ldg(wrow + p0), a0);
        a1 = fmaf(qs[k], __ldg(wrow + p1), a1);
    }
    if (ks == 0) {
        a0 += __ldg(bq + p0) + __ldg(bh + p0);
        a1 += __ldg(bq + p1) + __ldg(bh + p1);
    }
    atomicAdd(out + b * 512 + p0, a0);
    atomicAdd(out + b * 512 + p1, a1);
}

// ---------------- normalize: out[i] = e[i] / gsum[graph] ----------------
__global__ void __launch_bounds__(256) k_norm(
    const float* __restrict__ ebuf,
    const int* __restrict__ gidN, const int* __restrict__ gidE,
    const float* __restrict__ gsum, float* __restrict__ out) {
    const int base = blockIdx.x * 1024;
    const bool isNode = base < TN_;
    const int* gid = isNode ? gidN : gidE;
    const int lofs = isNode ? 0 : TN_;
    const int goff = isNode ? 0 : 64;
    const int t = threadIdx.x;
#pragma unroll
    for (int jj = 0; jj < 4; ++jj) {
        const int i = base + jj * 256 + t;
        const int g = goff + __ldg(gid + i - lofs);
        out[i] = __fdividef(__ldg(ebuf + i), __ldg(gsum + g));
    }
}

// ---------------- launch ----------------
extern "C" void kernel_launch(void* const* d_in, const int* in_sizes, int n_in,
                              void* d_out, int out_size) {
    const float* question = (const float*)d_in[0];
    const float* nodes    = (const float*)d_in[1];
    const float* edges    = (const float*)d_in[2];
    const float* W_nq     = (const float*)d_in[3];
    const float* b_nq     = (const float*)d_in[4];
    const float* W_n      = (const float*)d_in[5];
    const float* b_n      = (const float*)d_in[6];
    const float* w_nv     = (const float*)d_in[7];
    // d_in[8] = b_nv — softmax shift-invariant, unused
    const float* W_eq     = (const float*)d_in[9];
    const float* b_eq     = (const float*)d_in[10];
    const float* W_e      = (const float*)d_in[11];
    const float* b_e      = (const float*)d_in[12];
    const float* w_ev     = (const float*)d_in[13];
    // d_in[14] = b_ev — unused
    const int* node_gid   = (const int*)d_in[15];
    const int* edge_gid   = (const int*)d_in[16];
    float* out = (float*)d_out;

    float *qn, *qe, *part, *ebuf, *gsum;
    int* tctr;
    __nv_bfloat16 *wtn, *wte;
    cudaGetSymbolAddress((void**)&qn,   g_qn);
    cudaGetSymbolAddress((void**)&qe,   g_qe);
    cudaGetSymbolAddress((void**)&wtn,  g_wtn);
    cudaGetSymbolAddress((void**)&wte,  g_wte);
    cudaGetSymbolAddress((void**)&part, g_part);
    cudaGetSymbolAddress((void**)&ebuf, g_e);
    cudaGetSymbolAddress((void**)&gsum, g_sum);
    cudaGetSymbolAddress((void**)&tctr, g_tctr);

    cudaFuncSetAttribute(k_main, cudaFuncAttributeMaxDynamicSharedMemorySize, SMEM_BYTES);

    k_prep<<<551, 256>>>(W_n, W_e, wtn, wte, qn, qe, gsum, tctr);
    k_qproj<<<dim3(B_, 16, 2), 256>>>(question,
                                      W_nq, b_nq, b_n,
                                      W_eq, b_eq, b_e, qn, qe);

    k_main<<<dim3(4, NYN + TE_ / 256), 256, SMEM_BYTES>>>(
        nodes, edges, node_gid, edge_gid, wtn, wte, qn, qe, w_nv, w_ev,
        part, ebuf, gsum, tctr);

    k_norm<<<TT_ / 1024, 256>>>(ebuf, node_gid, edge_gid, gsum, out);
}

// round 17
// speedup vs baseline: 1.1137x; 1.0473x over previous
#include <cuda_runtime.h>
#include <cuda_bf16.h>
#include <cstdint>

#define DINLINE __device__ __forceinline__

// ---------------- problem sizes ----------------
#define B_  64
#define TN_ 131072
#define TE_ 262144
#define TT_ (TN_ + TE_)
#define QD_ 768
#define PD_ 512
#define KD_ 512

// ---------------- device scratch ----------------
__device__ float g_qn[B_ * PD_];
__device__ float g_qe[B_ * PD_];
__device__ __nv_bfloat16 g_wtn[PD_ * KD_];   // W_n transposed [P][K], bf16
__device__ __nv_bfloat16 g_wte[PD_ * KD_];
__device__ float g_part[4 * TT_];            // per-N-slice partial sums (no init needed)
__device__ float g_sum[128];                 // per-graph exp sums
__device__ int   g_ctr;                      // k_soft spin-barrier counter

// ---------------- helpers ----------------
DINLINE void cp16(uint32_t s, const void* g) {
    asm volatile("cp.async.cg.shared.global [%0], [%1], 16;"
                 :: "r"(s), "l"(g) : "memory");
}
DINLINE void cp_commit() { asm volatile("cp.async.commit_group;" ::: "memory"); }
template<int N> DINLINE void cp_wait() {
    asm volatile("cp.async.wait_group %0;" :: "n"(N) : "memory");
}

DINLINE uint32_t smem_u32(const void* p) {
    uint32_t a;
    asm("{ .reg .u64 t; cvta.to.shared.u64 t, %1; cvt.u32.u64 %0, t; }"
        : "=r"(a) : "l"(p));
    return a;
}

DINLINE float tanh_fast(float x) {
    float y;
    asm("tanh.approx.f32 %0, %1;" : "=f"(y) : "f"(x));
    return y;
}

DINLINE void mma_bf16(float* c, const uint32_t* a, const uint32_t* b) {
    asm volatile(
        "mma.sync.aligned.m16n8k16.row.col.f32.bf16.bf16.f32 "
        "{%0,%1,%2,%3}, {%4,%5,%6,%7}, {%8,%9}, {%0,%1,%2,%3};"
        : "+f"(c[0]), "+f"(c[1]), "+f"(c[2]), "+f"(c[3])
        : "r"(a[0]), "r"(a[1]), "r"(a[2]), "r"(a[3]),
          "r"(b[0]), "r"(b[1]));
}

DINLINE void ldm_x4(uint32_t& r0, uint32_t& r1, uint32_t& r2, uint32_t& r3,
                    uint32_t addr) {
    asm volatile("ldmatrix.sync.aligned.m8n8.x4.shared.b16 {%0,%1,%2,%3}, [%4];"
                 : "=r"(r0), "=r"(r1), "=r"(r2), "=r"(r3) : "r"(addr));
}

DINLINE uint32_t pack_bf16x2(float lo, float hi) {
    __nv_bfloat162 v = __float22bfloat162_rn(make_float2(lo, hi));
    return *reinterpret_cast<uint32_t*>(&v);
}

// ---------------- main fused GEMM (identical to R14 best) ----------------
#define ROWB   80u
#define ATILE  20480u
#define BTILE  10240u
#define BOFF   40960u
#define SM_OFF 71680u
#define SMEM_BYTES (71680 + 1024)
#define NYN 512              // node tiles in y

__global__ void __launch_bounds__(256, 1) k_main(
    const float* __restrict__ An, const float* __restrict__ Ae,
    const int* __restrict__ gidN, const int* __restrict__ gidE,
    const __nv_bfloat16* __restrict__ WtN, const __nv_bfloat16* __restrict__ WtE,
    const float* __restrict__ qN, const float* __restrict__ qE,
    const float* __restrict__ wvN, const float* __restrict__ wvE,
    float* __restrict__ part)
{
    extern __shared__ char smem[];
    float* s_sm = reinterpret_cast<float*>(smem + SM_OFF);

    const bool isNode = blockIdx.y < NYN;
    const int  ty     = isNode ? blockIdx.y : blockIdx.y - NYN;
    const float* __restrict__ A    = isNode ? An   : Ae;
    const int*   __restrict__ gid  = isNode ? gidN : gidE;
    const __nv_bfloat16* __restrict__ Wt = isNode ? WtN : WtE;
    const float* __restrict__ qeff = isNode ? qN   : qE;
    const float* __restrict__ wv   = isNode ? wvN  : wvE;
    const int    sOff = isNode ? 0 : TN_;

    const int tid  = threadIdx.x;
    const int lane = tid & 31;
    const int warp = tid >> 5;
    const int wm   = warp & 3;   // M block of 64
    const int wn   = warp >> 2;  // N block of 64

    const int mBase = ty * 256;
    const int nBase = blockIdx.x * 128;

    const uint32_t sb = smem_u32(smem);

    s_sm[tid] = 0.f;

    const int aRow = tid >> 3;
    const int aQ   = tid & 7;
    const float* Abase = A + (size_t)(mBase + aRow) * KD_ + aQ * 4;

    float4 ra[8];
    auto ldA = [&](int kc) {
        const float* p = Abase + kc * 32;
#pragma unroll
        for (int i = 0; i < 8; ++i)
            ra[i] = *reinterpret_cast<const float4*>(p + (size_t)i * 32 * KD_);
    };
    auto stsA = [&](int buf) {
        const uint32_t base = sb + buf * ATILE + aRow * ROWB + aQ * 8;
#pragma unroll
        for (int i = 0; i < 8; ++i) {
            uint32_t lo = pack_bf16x2(ra[i].x, ra[i].y);
            uint32_t hi = pack_bf16x2(ra[i].z, ra[i].w);
            asm volatile("st.shared.v2.b32 [%0], {%1,%2};"
                         :: "r"(base + i * 32 * ROWB), "r"(lo), "r"(hi) : "memory");
        }
    };
    const int bIdx0 = tid * 2;
    auto cpB = [&](int slot, int kc) {
#pragma unroll
        for (int j = 0; j < 2; ++j) {
            int idx = bIdx0 + j;
            int n = idx >> 2, g = idx & 3;
            cp16(sb + BOFF + slot * BTILE + n * ROWB + g * 16,
                 Wt + (size_t)(nBase + n) * KD_ + kc * 32 + g * 8);
        }
        cp_commit();
    };

    float c[4][8][4];
#pragma unroll
    for (int mt = 0; mt < 4; ++mt)
#pragma unroll
        for (int nt = 0; nt < 8; ++nt)
#pragma unroll
            for (int i = 0; i < 4; ++i) c[mt][nt][i] = 0.f;

    const int j = lane >> 3;
    const uint32_t aLane = (uint32_t)(wm * 64 + ((j & 1) << 3) + (lane & 7)) * ROWB
                         + (uint32_t)(j >> 1) * 16u;
    const uint32_t bLane = (uint32_t)(wn * 64 + ((j >> 1) << 3) + (lane & 7)) * ROWB
                         + (uint32_t)(j & 1) * 16u;

    uint32_t aF0[4][4], aF1[4][4];

    auto ldA_frags = [&](uint32_t aT2, uint32_t ko, uint32_t (&a)[4][4]) {
#pragma unroll
        for (int mt = 0; mt < 4; ++mt)
            ldm_x4(a[mt][0], a[mt][1], a[mt][2], a[mt][3],
                   aT2 + mt * 16 * ROWB + ko);
    };

    auto phase = [&](const uint32_t (&aIn)[4][4], uint32_t (&aOut)[4][4],
                     uint32_t bT2, uint32_t ko,
                     uint32_t aT2n, uint32_t kon, bool preloadA) {
        uint32_t b[2][2][2];
        ldm_x4(b[0][0][0], b[0][0][1], b[0][1][0], b[0][1][1], bT2 + ko);
#pragma unroll
        for (int p = 0; p < 4; ++p) {
            const int cb = p & 1, nb = cb ^ 1;
            if (p < 3) {
                ldm_x4(b[nb][0][0], b[nb][0][1], b[nb][1][0], b[nb][1][1],
                       bT2 + (uint32_t)(p + 1) * 16 * ROWB + ko);
            } else if (preloadA) {
                ldA_frags(aT2n, kon, aOut);
            }
#pragma unroll
            for (int mt = 0; mt < 4; ++mt) {
                mma_bf16(c[mt][2 * p],     aIn[mt], b[cb][0]);
                mma_bf16(c[mt][2 * p + 1], aIn[mt], b[cb][1]);
            }
        }
    };

    // ---- preamble ----
    ldA(0);
    cpB(0, 0);
    cpB(1, 1);
    stsA(0);
    ldA(1);
    cp_wait<1>();
    __syncthreads();
    ldA_frags(sb + aLane, 0, aF0);

#pragma unroll 1
    for (int kc = 0; kc < 16; ++kc) {
        const int abuf = kc & 1;
        if (kc + 2 < 16) cpB((kc + 2) % 3, kc + 2);

        const uint32_t aT2 = sb + abuf * ATILE + aLane;
        const uint32_t bT2 = sb + BOFF + (kc % 3) * BTILE + bLane;

        phase(aF0, aF1, bT2, 0, aT2, 32, true);
        if (kc + 1 < 16) stsA(abuf ^ 1);
        if (kc + 2 < 16) ldA(kc + 2);
        phase(aF1, aF0, bT2, 32, 0, 0, false);

        if (kc + 2 < 16) cp_wait<1>(); else cp_wait<0>();
        __syncthreads();
        if (kc + 1 < 16)
            ldA_frags(sb + (abuf ^ 1) * ATILE + aLane, 0, aF0);
    }

    // ---- epilogue: partial s[m] for this N-slice; no global atomics ----
    const int n0 = wn * 64 + 2 * (lane & 3);
#pragma unroll
    for (int mt = 0; mt < 4; ++mt) {
#pragma unroll
        for (int h = 0; h < 2; ++h) {
            const int row = wm * 64 + mt * 16 + (lane >> 2) + h * 8;
            const int g = __ldg(gid + mBase + row);
            const float* qrow = qeff + (size_t)g * PD_ + nBase;
            float s = 0.f;
#pragma unroll
            for (int nt = 0; nt < 8; ++nt) {
                const int nn = n0 + nt * 8;
                float2 q2 = *reinterpret_cast<const float2*>(qrow + nn);
                float2 w2 = *reinterpret_cast<const float2*>(wv + nBase + nn);
                float x0 = tanh_fast(c[mt][nt][h * 2 + 0] + q2.x);
                float x1 = tanh_fast(c[mt][nt][h * 2 + 1] + q2.y);
                s = fmaf(x0, w2.x, s);
                s = fmaf(x1, w2.y, s);
            }
            s += __shfl_xor_sync(0xffffffffu, s, 1);
            s += __shfl_xor_sync(0xffffffffu, s, 2);
            if ((lane & 3) == 0) atomicAdd(&s_sm[row], s);
        }
    }
    __syncthreads();
    part[(size_t)blockIdx.x * TT_ + sOff + mBase + tid] = s_sm[tid];
}

// ---------------- prep: transposes + qn/qe/gsum/ctr zeroing, one launch ----------------
__global__ void __launch_bounds__(256) k_prep(
    const float* __restrict__ Wn, const float* __restrict__ We,
    __nv_bfloat16* __restrict__ WtN, __nv_bfloat16* __restrict__ WtE,
    float* __restrict__ qn, float* __restrict__ qe,
    float* __restrict__ gsum, int* __restrict__ ctr) {
    const int blk = blockIdx.x;
    const int t = threadIdx.x;
    if (blk == 544) {
        if (t < 128) gsum[t] = 0.f;
        if (t == 128) *ctr = 0;
        return;
    }
    if (blk >= 512) {
        const int zi = blk - 512;
        float* dst = (zi < 16) ? (qn + zi * 2048) : (qe + (zi - 16) * 2048);
#pragma unroll
        for (int k = 0; k < 8; ++k) dst[k * 256 + t] = 0.f;
        return;
    }
    const bool isE = blk >= 256;
    const int b2 = blk & 255;
    const float* W = isE ? We : Wn;
    __nv_bfloat16* Wt = isE ? WtE : WtN;
    __shared__ float tile[32][33];
    const int tx = t & 31, ty2 = t >> 5;
    int x = (b2 & 15) * 32 + tx;
    int y = (b2 >> 4) * 32 + ty2;
#pragma unroll
    for (int j = 0; j < 32; j += 8)
        tile[ty2 + j][tx] = W[(y + j) * 512 + x];
    __syncthreads();
    int xo = (b2 >> 4) * 32 + tx;
    int yo = (b2 & 15) * 32 + ty2;
#pragma unroll
    for (int j = 0; j < 32; j += 8)
        Wt[(yo + j) * 512 + xo] = __float2bfloat16(tile[tx][ty2 + j]);
}

// split-k qproj, grid (B_, 16, 2): k-slice 48; z selects node/edge weights.
__global__ void __launch_bounds__(256) k_qproj(
    const float* __restrict__ q,
    const float* __restrict__ WqN, const float* __restrict__ bqN, const float* __restrict__ bhN,
    const float* __restrict__ WqE, const float* __restrict__ bqE, const float* __restrict__ bhE,
    float* __restrict__ outN, float* __restrict__ outE) {
    const float* Wq = blockIdx.z ? WqE : WqN;
    const float* bq = blockIdx.z ? bqE : bqN;
    const float* bh = blockIdx.z ? bhE : bhN;
    float* out = blockIdx.z ? outE : outN;
    __shared__ float qs[48];
    const int b = blockIdx.x, ks = blockIdx.y;
    const int k0 = ks * 48;
    const int t = threadIdx.x;
    if (t < 48) qs[t] = q[b * QD_ + k0 + t];
    __syncthreads();
    const int p0 = t, p1 = t + 256;
    float a0 = 0.f, a1 = 0.f;
#pragma unroll 4
    for (int k = 0; k < 48; ++k) {
        const float* wrow = Wq + (size_t)(k0 + k) * 512;
        a0 = fmaf(qs[k], __ldg(wrow + p0), a0);
        a1 = fmaf(qs[k], __ldg(wrow + p1), a1);
    }
    if (ks == 0) {
        a0 += __ldg(bq + p0) + __ldg(bh + p0);
        a1 += __ldg(bq + p1) + __ldg(bh + p1);
    }
    atomicAdd(out + b * 512 + p0, a0);
    atomicAdd(out + b * 512 + p1, a1);
}

// ---------------- fused softmax (no max-shift; |s| <= ~9 so exp is fp32-safe) ----
// Grid 192, each block handles chunks bx and bx+192 (2 x 1024 elems), fully
// unrolled so e-values/gids stay in registers across the spin barrier.
DINLINE void soft_chunk(const float* __restrict__ part,
                        const int* __restrict__ gidN, const int* __restrict__ gidE,
                        float* ssum, int t, int chunk,
                        float (&ev)[4], int (&gv)[4]) {
    const int base = chunk * 1024;
    const bool isNode = base < TN_;          // 1024 divides TN_: no straddle
    const int* gid = isNode ? gidN : gidE;
    const int lofs = isNode ? 0 : TN_;
    const int goff = isNode ? 0 : 64;
#pragma unroll
    for (int jj = 0; jj < 4; ++jj) {
        const int i = base + jj * 256 + t;
        float v = __ldg(part + i)
                + __ldg(part + TT_ + i)
                + __ldg(part + 2 * TT_ + i)
                + __ldg(part + 3 * TT_ + i);
        float e = __expf(v);
        ev[jj] = e;
        const int g = __ldg(gid + i - lofs);
        gv[jj] = goff + g;
        const int g0 = __shfl_sync(0xffffffffu, g, 0);
        if (__all_sync(0xffffffffu, g == g0)) {
            float r = e;
            r += __shfl_xor_sync(0xffffffffu, r, 16);
            r += __shfl_xor_sync(0xffffffffu, r, 8);
            r += __shfl_xor_sync(0xffffffffu, r, 4);
            r += __shfl_xor_sync(0xffffffffu, r, 2);
            r += __shfl_xor_sync(0xffffffffu, r, 1);
            if ((t & 31) == 0) atomicAdd(&ssum[goff + g0], r);
        } else {
            atomicAdd(&ssum[goff + g], e);
        }
    }
}

__global__ void __launch_bounds__(256) k_soft(
    const float* __restrict__ part,
    const int* __restrict__ gidN, const int* __restrict__ gidE,
    float* __restrict__ gsum, int* __restrict__ ctr,
    float* __restrict__ out) {
    __shared__ float ssum[128];
    const int t = threadIdx.x;
    if (t < 128) ssum[t] = 0.f;
    __syncthreads();

    float ev0[4], ev1[4];
    int   gv0[4], gv1[4];
    soft_chunk(part, gidN, gidE, ssum, t, blockIdx.x,       ev0, gv0);
    soft_chunk(part, gidN, gidE, ssum, t, blockIdx.x + 192, ev1, gv1);
    __syncthreads();
    if (t < 128 && ssum[t] != 0.f) atomicAdd(&gsum[t], ssum[t]);

    // ---- device-wide barrier (192 blocks, all co-resident) ----
    __threadfence();
    __syncthreads();
    if (t == 0) {
        atomicAdd(ctr, 1);
        volatile int* vc = ctr;
        while (*vc < (int)gridDim.x) { }
    }
    __syncthreads();
    __threadfence();

    // ---- stage final sums in smem, then normalize from registers ----
    if (t < 128) ssum[t] = __ldcg(gsum + t);
    __syncthreads();

    const int base0 = blockIdx.x * 1024;
    const int base1 = (blockIdx.x + 192) * 1024;
#pragma unroll
    for (int jj = 0; jj < 4; ++jj)
        out[base0 + jj * 256 + t] = __fdividef(ev0[jj], ssum[gv0[jj]]);
#pragma unroll
    for (int jj = 0; jj < 4; ++jj)
        out[base1 + jj * 256 + t] = __fdividef(ev1[jj], ssum[gv1[jj]]);
}

// ---------------- launch ----------------
extern "C" void kernel_launch(void* const* d_in, const int* in_sizes, int n_in,
                              void* d_out, int out_size) {
    const float* question = (const float*)d_in[0];
    const float* nodes    = (const float*)d_in[1];
    const float* edges    = (const float*)d_in[2];
    const float* W_nq     = (const float*)d_in[3];
    const float* b_nq     = (const float*)d_in[4];
    const float* W_n      = (const float*)d_in[5];
    const float* b_n      = (const float*)d_in[6];
    const float* w_nv     = (const float*)d_in[7];
    // d_in[8] = b_nv — softmax shift-invariant, unused
    const float* W_eq     = (const float*)d_in[9];
    const float* b_eq     = (const float*)d_in[10];
    const float* W_e      = (const float*)d_in[11];
    const float* b_e      = (const float*)d_in[12];
    const float* w_ev     = (const float*)d_in[13];
    // d_in[14] = b_ev — unused
    const int* node_gid   = (const int*)d_in[15];
    const int* edge_gid   = (const int*)d_in[16];
    float* out = (float*)d_out;

    float *qn, *qe, *part, *gsum;
    int* ctr;
    __nv_bfloat16 *wtn, *wte;
    cudaGetSymbolAddress((void**)&qn,   g_qn);
    cudaGetSymbolAddress((void**)&qe,   g_qe);
    cudaGetSymbolAddress((void**)&wtn,  g_wtn);
    cudaGetSymbolAddress((void**)&wte,  g_wte);
    cudaGetSymbolAddress((void**)&part, g_part);
    cudaGetSymbolAddress((void**)&gsum, g_sum);
    cudaGetSymbolAddress((void**)&ctr,  g_ctr);

    cudaFuncSetAttribute(k_main, cudaFuncAttributeMaxDynamicSharedMemorySize, SMEM_BYTES);

    k_prep<<<545, 256>>>(W_n, W_e, wtn, wte, qn, qe, gsum, ctr);
    k_qproj<<<dim3(B_, 16, 2), 256>>>(question,
                                      W_nq, b_nq, b_n,
                                      W_eq, b_eq, b_e, qn, qe);

    k_main<<<dim3(4, NYN + TE_ / 256), 256, SMEM_BYTES>>>(
        nodes, edges, node_gid, edge_gid, wtn, wte, qn, qe, w_nv, w_ev, part);

    k_soft<<<192, 256>>>(part, node_gid, edge_gid, gsum, ctr, out);
}